// round 7
// baseline (speedup 1.0000x reference)
#include <cuda_runtime.h>
#include <cuda_bf16.h>
#include <cstdint>

#define NTOK 65
#define MTOK 129
#define NHEAD 16
#define HDIM 64
#define CDIM 1024

// fp32 intermediates
__device__ float g_q [512 * NTOK * CDIM];
__device__ float g_kv[512 * MTOK * 2 * CDIM];
__device__ float g_ao[512 * NTOK * CDIM];
// tf32-rounded, k-permuted weights [N][perm(K)]
__device__ float g_wqt [CDIM * CDIM];
__device__ float g_wkvt[2 * CDIM * CDIM];
__device__ float g_wpt [CDIM * CDIM];

__device__ __forceinline__ unsigned f2tf32(float x) {
    unsigned r;
    asm("cvt.rna.tf32.f32 %0, %1;" : "=r"(r) : "f"(x));
    return r;
}
__device__ __forceinline__ void cp16s(uint32_t s, const float* g) {
    asm volatile("cp.async.cg.shared.global [%0], [%1], 16;"
                 :: "r"(s), "l"(g) : "memory");
}
__device__ __forceinline__ uint32_t smem_u32(const void* p) {
    uint32_t a;
    asm("{ .reg .u64 t; cvta.to.shared.u64 t, %1; cvt.u32.u64 %0, t; }"
        : "=r"(a) : "l"(p));
    return a;
}

// ---------------------------------------------------------------------------
// W[K][N] fp32 -> Wt[N][perm(K)] tf32-rounded; perm within 8-groups:
// p(k) = (k&~7)|((k&3)<<1)|((k>>2)&1)  (fragment pairs (t,t+4) adjacent)
// ---------------------------------------------------------------------------
__global__ __launch_bounds__(256) void transpose_tf32_perm(
    const float* __restrict__ W, float* __restrict__ Wt, int K, int N)
{
    __shared__ float t[32][33];
    const int n0 = blockIdx.x * 32, k0 = blockIdx.y * 32;
    const int tx = threadIdx.x & 31, ty = threadIdx.x >> 5;   // 32x8
    #pragma unroll
    for (int i = 0; i < 4; i++)
        t[ty + 8 * i][tx] = W[(size_t)(k0 + ty + 8 * i) * N + n0 + tx];
    __syncthreads();
    const int pk = (tx & ~7) | ((tx & 3) << 1) | ((tx >> 2) & 1);
    #pragma unroll
    for (int i = 0; i < 4; i++)
        Wt[(size_t)(n0 + ty + 8 * i) * K + k0 + pk] =
            __uint_as_float(f2tf32(t[tx][ty + 8 * i]));
}

// ---------------------------------------------------------------------------
// tf32 mma.sync GEMM: C[M,N] = A[M,K] @ Bt[N,K]^T + bias[N]
// Block tile 128x256, 8 warps (2M x 4N), warp tile 64x64, K-tile 32.
// A: raw fp32 LDG -> regs -> cvt.rna+perm -> STS (manual double buffer).
// B: pre-rounded/permuted weights via cp.async.
// Smem row stride 40 words: LDS.64 fragment reads conflict-free.
// ---------------------------------------------------------------------------
#define GS 40
#define A_W (128 * GS)            // 5120 words
#define B_W (256 * GS)            // 10240 words
#define STG_W (A_W + B_W)         // words per stage

__global__ __launch_bounds__(256, 1) void gemm_mma(
    const float* __restrict__ A, const float* __restrict__ Bt,
    const float* __restrict__ bias, float* __restrict__ C,
    int M, int N, int K)
{
    extern __shared__ float smg[];    // [2][STG_W] = 122880 B

    const int tid  = threadIdx.x;
    const int lane = tid & 31;
    const int warp = tid >> 5;
    const int wm   = warp >> 2;       // 0..1
    const int wn   = warp & 3;        // 0..3
    const int g    = lane >> 2;       // 0..7
    const int t    = lane & 3;        // 0..3

    const int bn = blockIdx.x, bm = blockIdx.y;
    const float* Ag = A  + (size_t)bm * 128 * K;
    const float* Bg = Bt + (size_t)bn * 256 * K;
    const uint32_t sb = smem_u32(smg);

    // A staging: thread owns row arow, 16 consecutive k starting at akh
    const int arow = tid >> 1;
    const int akh  = (tid & 1) * 16;
    const float* aptr = Ag + (size_t)arow * K + akh;

    float4 r0, r1, r2, r3;            // A prefetch regs (16 floats)
    auto ldgA = [&](int kt) {
        const float* p = aptr + kt;
        r0 = *(const float4*)(p);
        r1 = *(const float4*)(p + 4);
        r2 = *(const float4*)(p + 8);
        r3 = *(const float4*)(p + 12);
    };
    auto stsA = [&](int s) {          // cvt.rna + perm, 4x STS.128
        float* dst = smg + s * STG_W + arow * GS + akh;
        uint4 w;
        w.x = f2tf32(r0.x); w.y = f2tf32(r1.x); w.z = f2tf32(r0.y); w.w = f2tf32(r1.y);
        *(uint4*)(dst)     = w;
        w.x = f2tf32(r0.z); w.y = f2tf32(r1.z); w.z = f2tf32(r0.w); w.w = f2tf32(r1.w);
        *(uint4*)(dst + 4) = w;
        w.x = f2tf32(r2.x); w.y = f2tf32(r3.x); w.z = f2tf32(r2.y); w.w = f2tf32(r3.y);
        *(uint4*)(dst + 8) = w;
        w.x = f2tf32(r2.z); w.y = f2tf32(r3.z); w.z = f2tf32(r2.w); w.w = f2tf32(r3.w);
        *(uint4*)(dst + 12) = w;
    };
    auto cpB = [&](int kt, int s) {   // 256 rows x 8 chunks = 2048 cp16
        const uint32_t base = sb + (s * STG_W + A_W) * 4;
        #pragma unroll
        for (int it = 0; it < 8; it++) {
            int idx = tid + it * 256;
            int row = idx >> 3, c = idx & 7;
            cp16s(base + (row * GS + c * 4) * 4,
                  Bg + (size_t)row * K + kt + c * 4);
        }
        asm volatile("cp.async.commit_group;" ::: "memory");
    };

    float acc[4][8][4];
    #pragma unroll
    for (int i = 0; i < 4; i++)
        #pragma unroll
        for (int j = 0; j < 8; j++)
            #pragma unroll
            for (int r = 0; r < 4; r++) acc[i][j][r] = 0.f;

    const int NT = K >> 5;            // 32
    // prologue
    ldgA(0);
    cpB(0, 0);
    stsA(0);
    if (NT > 1) ldgA(32);
    asm volatile("cp.async.wait_group 0;" ::: "memory");
    __syncthreads();

    for (int ti = 0; ti < NT; ti++) {
        const int cur = ti & 1;
        if (ti + 1 < NT) {
            stsA(cur ^ 1);            // regs hold tile ti+1
            cpB((ti + 1) << 5, cur ^ 1);
            if (ti + 2 < NT) ldgA((ti + 2) << 5);
        }

        const float* As = smg + cur * STG_W;
        const float* Bs = As + A_W;
        #pragma unroll
        for (int ks = 0; ks < 4; ks++) {
            const int k0 = ks * 8 + 2 * t;
            unsigned af[4][4];
            #pragma unroll
            for (int i = 0; i < 4; i++) {
                int r = wm * 64 + i * 16 + g;
                uint2 lo = *(const uint2*)(As + r * GS + k0);
                uint2 hi = *(const uint2*)(As + (r + 8) * GS + k0);
                af[i][0] = lo.x; af[i][2] = lo.y;
                af[i][1] = hi.x; af[i][3] = hi.y;
            }
            unsigned bf[8][2];
            #pragma unroll
            for (int j = 0; j < 8; j++) {
                int n = wn * 64 + j * 8 + g;
                uint2 bb = *(const uint2*)(Bs + n * GS + k0);
                bf[j][0] = bb.x; bf[j][1] = bb.y;
            }
            #pragma unroll
            for (int i = 0; i < 4; i++)
                #pragma unroll
                for (int j = 0; j < 8; j++) {
                    asm volatile(
                        "mma.sync.aligned.m16n8k8.row.col.f32.tf32.tf32.f32 "
                        "{%0,%1,%2,%3}, {%4,%5,%6,%7}, {%8,%9}, {%0,%1,%2,%3};"
                        : "+f"(acc[i][j][0]), "+f"(acc[i][j][1]),
                          "+f"(acc[i][j][2]), "+f"(acc[i][j][3])
                        : "r"(af[i][0]), "r"(af[i][1]), "r"(af[i][2]), "r"(af[i][3]),
                          "r"(bf[j][0]), "r"(bf[j][1]));
                }
        }

        if (ti + 1 < NT)
            asm volatile("cp.async.wait_group 0;" ::: "memory");
        __syncthreads();
    }

    #pragma unroll
    for (int i = 0; i < 4; i++) {
        int row0 = bm * 128 + wm * 64 + i * 16 + g;
        #pragma unroll
        for (int j = 0; j < 8; j++) {
            int col = bn * 256 + wn * 64 + j * 8 + t * 2;
            float b0 = bias[col], b1 = bias[col + 1];
            float2 v0 = make_float2(acc[i][j][0] + b0, acc[i][j][1] + b1);
            float2 v1 = make_float2(acc[i][j][2] + b0, acc[i][j][3] + b1);
            *(float2*)(C + (size_t)row0 * N + col)       = v0;
            *(float2*)(C + (size_t)(row0 + 8) * N + col) = v1;
        }
    }
}

// ---------------------------------------------------------------------------
// Fused attention (R4 core, raw fp32 output — P GEMM rounds during staging)
// ---------------------------------------------------------------------------
#define KSTR 68
#define VSTR 132
#define PSTR 132

__global__ __launch_bounds__(256) void attn_kernel(
    const float* __restrict__ q, const float* __restrict__ kv,
    const int* __restrict__ mask_l,
    const int* __restrict__ mask_r,
    const int* __restrict__ nW_ptr,
    const float* __restrict__ rel_table,
    const float* __restrict__ cls_self,
    const float* __restrict__ cls_up,
    const float* __restrict__ cls_down,
    float* __restrict__ ao)
{
    const int h = blockIdx.x;
    const int b = blockIdx.y;
    const int tid = threadIdx.x;
    const int lane = tid & 31;
    const int warp = tid >> 5;

    extern __shared__ float sm[];
    float* Ks = sm;
    float* Vt = Ks + MTOK * KSTR;
    float* Qs = Vt + HDIM * VSTR;
    float* Ps = Qs + NTOK * HDIM;
    float* tb = Ps + 8 * 2 * PSTR;

    for (int i = tid; i < 191; i += 256) tb[i] = rel_table[i * NHEAD + h];
    if (tid == 0) tb[191] = cls_self[h];
    for (int i = tid; i < 128; i += 256) tb[192 + i] = cls_up[h * (MTOK - 1) + i];
    for (int i = tid; i < 64; i += 256) tb[320 + i] = cls_down[h * (NTOK - 1) + i];

    const float* kvb = kv + (size_t)b * MTOK * 2 * CDIM + h * HDIM;
    for (int idx = tid; idx < MTOK * 16; idx += 256) {
        int m = idx >> 4, d4 = (idx & 15) << 2;
        float4 kk = *(const float4*)(kvb + (size_t)m * 2048 + d4);
        *(float4*)(Ks + m * KSTR + d4) = kk;
        float4 vv = *(const float4*)(kvb + (size_t)m * 2048 + CDIM + d4);
        Vt[(d4 + 0) * VSTR + m] = vv.x;
        Vt[(d4 + 1) * VSTR + m] = vv.y;
        Vt[(d4 + 2) * VSTR + m] = vv.z;
        Vt[(d4 + 3) * VSTR + m] = vv.w;
    }
    const float* qb = q + (size_t)b * NTOK * CDIM + h * HDIM;
    for (int idx = tid; idx < NTOK * 16; idx += 256) {
        int n = idx >> 4, d4 = (idx & 15) << 2;
        *(float4*)(Qs + n * HDIM + d4) = *(const float4*)(qb + (size_t)n * CDIM + d4);
    }
    __syncthreads();

    const int nW = *nW_ptr;
    const int mc = (nW < 2) ? nW : 2;
    const int w = b % nW;
    const bool use_l = (w < mc);
    const bool use_r = (w >= nW - mc);
    const int* ml = mask_l + (size_t)w * NTOK * MTOK;
    const int* mr = mask_r + (size_t)(2 - mc + (w - (nW - mc))) * NTOK * MTOK;

    const float scale = 0.125f;
    const float NEG = -3.402823466e38f;

    for (int n0 = warp * 2; n0 < NTOK; n0 += 16) {
        const bool two = (n0 + 1 < NTOK);
        const int n1 = two ? n0 + 1 : n0;
        const int nm = (lane == 0) ? 5 : 4;
        float s0[5], s1[5];
        const float4* q0 = (const float4*)(Qs + n0 * HDIM);
        const float4* q1 = (const float4*)(Qs + n1 * HDIM);

        for (int j = 0; j < nm; j++) {
            const int m = lane + 32 * j;
            const float4* kr = (const float4*)(Ks + m * KSTR);
            float a0 = 0.f, a1 = 0.f;
            #pragma unroll
            for (int d4 = 0; d4 < 16; d4++) {
                float4 kvv = kr[d4];
                float4 qa = q0[d4];
                float4 qc = q1[d4];
                a0 = fmaf(kvv.x, qa.x, fmaf(kvv.y, qa.y,
                     fmaf(kvv.z, qa.z, fmaf(kvv.w, qa.w, a0))));
                a1 = fmaf(kvv.x, qc.x, fmaf(kvv.y, qc.y,
                     fmaf(kvv.z, qc.z, fmaf(kvv.w, qc.w, a1))));
            }
            a0 *= scale; a1 *= scale;

            float bias0 = (n0 == 0)
                ? ((m == 0) ? tb[191] : tb[192 + m - 1])
                : ((m == 0) ? tb[320 + n0 - 1] : tb[n0 - m + 127]);
            float bias1 = (n1 == 0)
                ? ((m == 0) ? tb[191] : tb[192 + m - 1])
                : ((m == 0) ? tb[320 + n1 - 1] : tb[n1 - m + 127]);
            a0 += bias0; a1 += bias1;

            bool m0 = false, m1 = false;
            if (use_l) { m0 = ml[n0 * MTOK + m] != 0; m1 = ml[n1 * MTOK + m] != 0; }
            if (use_r) { m0 = m0 || (mr[n0 * MTOK + m] != 0);
                         m1 = m1 || (mr[n1 * MTOK + m] != 0); }
            s0[j] = m0 ? NEG : a0;
            s1[j] = m1 ? NEG : a1;
        }

        float* Prow0 = Ps + warp * 2 * PSTR;
        float* Prow1 = Prow0 + PSTR;
        {
            float mx = s0[0];
            for (int j = 1; j < nm; j++) mx = fmaxf(mx, s0[j]);
            #pragma unroll
            for (int o = 16; o; o >>= 1) mx = fmaxf(mx, __shfl_xor_sync(~0u, mx, o));
            float sum = 0.f, p[5];
            for (int j = 0; j < nm; j++) { p[j] = __expf(s0[j] - mx); sum += p[j]; }
            #pragma unroll
            for (int o = 16; o; o >>= 1) sum += __shfl_xor_sync(~0u, sum, o);
            float inv = 1.f / sum;
            for (int j = 0; j < nm; j++) Prow0[lane + 32 * j] = p[j] * inv;
        }
        {
            float mx = s1[0];
            for (int j = 1; j < nm; j++) mx = fmaxf(mx, s1[j]);
            #pragma unroll
            for (int o = 16; o; o >>= 1) mx = fmaxf(mx, __shfl_xor_sync(~0u, mx, o));
            float sum = 0.f, p[5];
            for (int j = 0; j < nm; j++) { p[j] = __expf(s1[j] - mx); sum += p[j]; }
            #pragma unroll
            for (int o = 16; o; o >>= 1) sum += __shfl_xor_sync(~0u, sum, o);
            float inv = 1.f / sum;
            for (int j = 0; j < nm; j++) Prow1[lane + 32 * j] = p[j] * inv;
        }
        __syncwarp();

        float o00 = 0.f, o01 = 0.f, o10 = 0.f, o11 = 0.f;
        const float4* v0 = (const float4*)(Vt + lane * VSTR);
        const float4* v1 = (const float4*)(Vt + (lane + 32) * VSTR);
        const float4* p0 = (const float4*)Prow0;
        const float4* p1 = (const float4*)Prow1;
        #pragma unroll
        for (int m4 = 0; m4 < 32; m4++) {
            float4 va = v0[m4], vb = v1[m4];
            float4 pa = p0[m4], pb = p1[m4];
            o00 = fmaf(pa.x, va.x, fmaf(pa.y, va.y, fmaf(pa.z, va.z, fmaf(pa.w, va.w, o00))));
            o01 = fmaf(pa.x, vb.x, fmaf(pa.y, vb.y, fmaf(pa.z, vb.z, fmaf(pa.w, vb.w, o01))));
            o10 = fmaf(pb.x, va.x, fmaf(pb.y, va.y, fmaf(pb.z, va.z, fmaf(pb.w, va.w, o10))));
            o11 = fmaf(pb.x, vb.x, fmaf(pb.y, vb.y, fmaf(pb.z, vb.z, fmaf(pb.w, vb.w, o11))));
        }
        {
            float pt0 = Prow0[128], pt1 = Prow1[128];
            float va = Vt[lane * VSTR + 128], vb = Vt[(lane + 32) * VSTR + 128];
            o00 = fmaf(pt0, va, o00); o01 = fmaf(pt0, vb, o01);
            o10 = fmaf(pt1, va, o10); o11 = fmaf(pt1, vb, o11);
        }

        float* aor0 = ao + ((size_t)b * NTOK + n0) * CDIM + h * HDIM;
        aor0[lane]      = o00;
        aor0[lane + 32] = o01;
        if (two) {
            float* aor1 = ao + ((size_t)b * NTOK + n1) * CDIM + h * HDIM;
            aor1[lane]      = o10;
            aor1[lane + 32] = o11;
        }
        __syncwarp();
    }
}

// ---------------------------------------------------------------------------
extern "C" void kernel_launch(void* const* d_in, const int* in_sizes, int n_in,
                              void* d_out, int out_size)
{
    const float* x        = (const float*)d_in[0];
    const float* x_       = (const float*)d_in[1];
    const int*   mask_l   = (const int*)d_in[2];
    const int*   mask_r   = (const int*)d_in[3];
    const int*   nW_ptr   = (const int*)d_in[4];
    const float* Wq       = (const float*)d_in[5];
    const float* bq       = (const float*)d_in[6];
    const float* Wkv      = (const float*)d_in[7];
    const float* bkv      = (const float*)d_in[8];
    const float* Wp       = (const float*)d_in[9];
    const float* bp       = (const float*)d_in[10];
    const float* rel      = (const float*)d_in[11];
    const float* cls_self = (const float*)d_in[12];
    const float* cls_up   = (const float*)d_in[13];
    const float* cls_down = (const float*)d_in[14];

    const int BnW = in_sizes[0] / (NTOK * CDIM);   // 512
    const int Mq  = BnW * NTOK;                    // 33280
    const int Mkv = BnW * MTOK;                    // 66048

    float *qbuf, *kvbuf, *aobuf, *wqt, *wkvt, *wpt;
    cudaGetSymbolAddress((void**)&qbuf,  g_q);
    cudaGetSymbolAddress((void**)&kvbuf, g_kv);
    cudaGetSymbolAddress((void**)&aobuf, g_ao);
    cudaGetSymbolAddress((void**)&wqt,   g_wqt);
    cudaGetSymbolAddress((void**)&wkvt,  g_wkvt);
    cudaGetSymbolAddress((void**)&wpt,   g_wpt);

    // weights -> [N][perm(K)] tf32-rounded (small; activations are fused)
    transpose_tf32_perm<<<dim3(CDIM / 32, CDIM / 32), 256>>>(Wq, wqt, CDIM, CDIM);
    transpose_tf32_perm<<<dim3(2 * CDIM / 32, CDIM / 32), 256>>>(Wkv, wkvt, CDIM, 2 * CDIM);
    transpose_tf32_perm<<<dim3(CDIM / 32, CDIM / 32), 256>>>(Wp, wpt, CDIM, CDIM);

    const int gsm = 2 * STG_W * sizeof(float);     // 122880
    cudaFuncSetAttribute(gemm_mma, cudaFuncAttributeMaxDynamicSharedMemorySize, gsm);

    gemm_mma<<<dim3(CDIM / 256, Mq / 128), 256, gsm>>>(x, wqt, bq, qbuf, Mq, CDIM, CDIM);
    gemm_mma<<<dim3(2 * CDIM / 256, Mkv / 128), 256, gsm>>>(x_, wkvt, bkv, kvbuf, Mkv, 2 * CDIM, CDIM);

    const int attn_smem = (MTOK * KSTR + HDIM * VSTR + NTOK * HDIM
                           + 8 * 2 * PSTR + 392) * sizeof(float);
    cudaFuncSetAttribute(attn_kernel, cudaFuncAttributeMaxDynamicSharedMemorySize, attn_smem);
    attn_kernel<<<dim3(NHEAD, BnW), 256, attn_smem>>>(
        qbuf, kvbuf, mask_l, mask_r, nW_ptr, rel, cls_self, cls_up, cls_down, aobuf);

    gemm_mma<<<dim3(CDIM / 256, Mq / 128), 256, gsm>>>(aobuf, wpt, bp, (float*)d_out, Mq, CDIM, CDIM);
}